// round 6
// baseline (speedup 1.0000x reference)
#include <cuda_runtime.h>
#include <cstdint>

#define HW       65536
#define NPIX     (16 * HW)
#define TPB      192
#define TILE_PX  128
#define TILES_PER_BLK 4
#define NBLK     (NPIX / (TILE_PX * TILES_PER_BLK))   // 2048

typedef unsigned long long u64;

__device__ __forceinline__ u64 ffma2(u64 a, u64 b, u64 c) {
    u64 d;
    asm("fma.rn.f32x2 %0, %1, %2, %3;" : "=l"(d) : "l"(a), "l"(b), "l"(c));
    return d;
}
__device__ __forceinline__ u64 pack2(float lo, float hi) {
    u64 d;
    asm("mov.b64 %0, {%1, %2};" : "=l"(d) : "f"(lo), "f"(hi));
    return d;
}
__device__ __forceinline__ void unpack2(u64 v, float& lo, float& hi) {
    asm("mov.b64 {%0, %1}, %2;" : "=f"(lo), "=f"(hi) : "l"(v));
}

// ---- dynamic smem (float units) ----
#define F_SW    0                       // [64][96]  conv weights transposed
#define F_SOUT  6144                    // [96][128] conv outputs
#define F_SBIAS (F_SOUT + 12288)        // [96] k|v|q bias
#define F_SB3   (F_SBIAS + 96)          // [16]
#define F_SSCL  (F_SB3 + 16)            // [1] + pad
#define F_TOTAL (F_SSCL + 4)
#define SMEM_BYTES (F_TOTAL * 4)        // 74,256 B -> 3 CTAs/SM

__global__ void __launch_bounds__(TPB, 3)
fused_tiled_kernel(
    const float* __restrict__ kv_in, const float* __restrict__ q_in,
    const float* __restrict__ key_w, const float* __restrict__ key_b,
    const float* __restrict__ value_w, const float* __restrict__ value_b,
    const float* __restrict__ query_w, const float* __restrict__ query_b,
    const float* __restrict__ scale_p,
    const float* __restrict__ d1_w, const float* __restrict__ d2_w,
    const float* __restrict__ d3_w, const float* __restrict__ d3_b,
    float* __restrict__ out)
{
    extern __shared__ __align__(16) float sm[];
    float* sW    = sm + F_SW;
    float* sOut  = sm + F_SOUT;
    float* sBias = sm + F_SBIAS;
    float* sB3   = sm + F_SB3;
    float* sScl  = sm + F_SSCL;

    const int tid  = threadIdx.x;
    const int wid  = tid >> 5;     // 0..5 : out-group of 16
    const int lane = tid & 31;     // px-group of 4
    const int px0  = lane * 4;

    // ---- one-time: stage conv weights (transposed) + biases ----
    for (int i = tid; i < 96 * 64; i += TPB) {
        int o = i >> 6, c = i & 63;
        float w = (o < 32) ? key_w[o * 64 + c]
                : (o < 64) ? value_w[(o - 32) * 64 + c]
                           : query_w[(o - 64) * 64 + c];
        sW[c * 96 + o] = w;
    }
    if (tid < 32) {
        sBias[tid]      = key_b[tid];
        sBias[32 + tid] = value_b[tid];
        sBias[64 + tid] = query_b[tid];
    }
    if (tid < 16) sB3[tid] = d3_b[tid];
    if (tid == 0) sScl[0] = scale_p[0];
    __syncthreads();

    for (int t = 0; t < TILES_PER_BLK; ++t) {
        const int tile = blockIdx.x * TILES_PER_BLK + t;
        const int p0   = tile * TILE_PX;
        const int b    = p0 >> 16;
        const int poff = p0 & (HW - 1);

        // ---- conv: warp w -> outs [16w, 16w+16), thread: 4 px x 16 outs ----
        const float* src = ((wid < 4) ? kv_in : q_in)
                         + (size_t)b * 64 * HW + poff + px0;

        u64 acc[4][8];   // [px][out-pair]
        {
            const u64* bp = reinterpret_cast<const u64*>(sBias) + wid * 8;
            #pragma unroll
            for (int j = 0; j < 8; ++j) {
                u64 bj = bp[j];
                acc[0][j] = bj; acc[1][j] = bj; acc[2][j] = bj; acc[3][j] = bj;
            }
        }

        #pragma unroll 2
        for (int c = 0; c < 64; ++c) {
            float4 a = __ldg(reinterpret_cast<const float4*>(src + (size_t)c * HW));
            const u64* wp = reinterpret_cast<const u64*>(&sW[c * 96 + wid * 16]);
            u64 w[8];
            #pragma unroll
            for (int j = 0; j < 8; ++j) w[j] = wp[j];
            u64 a0 = pack2(a.x, a.x);
            u64 a1 = pack2(a.y, a.y);
            u64 a2 = pack2(a.z, a.z);
            u64 a3 = pack2(a.w, a.w);
            #pragma unroll
            for (int j = 0; j < 8; ++j) {
                acc[0][j] = ffma2(a0, w[j], acc[0][j]);
                acc[1][j] = ffma2(a1, w[j], acc[1][j]);
                acc[2][j] = ffma2(a2, w[j], acc[2][j]);
                acc[3][j] = ffma2(a3, w[j], acc[3][j]);
            }
        }

        // ---- redistribute: sOut[out][px] ----
        #pragma unroll
        for (int j = 0; j < 8; ++j) {
            float l0, h0, l1, h1, l2, h2, l3, h3;
            unpack2(acc[0][j], l0, h0);
            unpack2(acc[1][j], l1, h1);
            unpack2(acc[2][j], l2, h2);
            unpack2(acc[3][j], l3, h3);
            int o0 = 16 * wid + 2 * j;
            *reinterpret_cast<float4*>(&sOut[o0 * TILE_PX + px0]) =
                make_float4(l0, l1, l2, l3);
            *reinterpret_cast<float4*>(&sOut[(o0 + 1) * TILE_PX + px0]) =
                make_float4(h0, h1, h2, h3);
        }
        __syncthreads();

        // ---- epilogue: threads 0..127, one pixel each ----
        if (tid < TILE_PX) {
            const int px = tid;
            const float scl = sScl[0];

            float x[32];
            #pragma unroll
            for (int o = 0; o < 32; ++o) {
                float kk = sOut[o * TILE_PX + px];
                float vv = sOut[(32 + o) * TILE_PX + px];
                float qq = sOut[(64 + o) * TILE_PX + px];
                float z = kk * qq * scl;
                float g = __fdividef(1.0f, 1.0f + __expf(-z));
                x[o] = g * vv;
            }

            // d1: 32->16 relu   (rows of d1_w via uniform __ldg float4)
            float h1[16];
            #pragma unroll
            for (int o = 0; o < 16; ++o) {
                const float4* wr = reinterpret_cast<const float4*>(d1_w + o * 32);
                float s0 = 0.f;
                #pragma unroll
                for (int j = 0; j < 8; ++j) {
                    float4 w = __ldg(wr + j);
                    s0 = fmaf(x[4*j+0], w.x, s0);
                    s0 = fmaf(x[4*j+1], w.y, s0);
                    s0 = fmaf(x[4*j+2], w.z, s0);
                    s0 = fmaf(x[4*j+3], w.w, s0);
                }
                h1[o] = fmaxf(s0, 0.0f);
            }

            // d2: 16->8 relu
            float h2[8];
            #pragma unroll
            for (int o = 0; o < 8; ++o) {
                const float4* wr = reinterpret_cast<const float4*>(d2_w + o * 16);
                float s0 = 0.f;
                #pragma unroll
                for (int j = 0; j < 4; ++j) {
                    float4 w = __ldg(wr + j);
                    s0 = fmaf(h1[4*j+0], w.x, s0);
                    s0 = fmaf(h1[4*j+1], w.y, s0);
                    s0 = fmaf(h1[4*j+2], w.z, s0);
                    s0 = fmaf(h1[4*j+3], w.w, s0);
                }
                h2[o] = fmaxf(s0, 0.0f);
            }

            // d3: 8->16 + bias, store
            float* op = out + ((size_t)b * 16) * HW + poff + px;
            #pragma unroll
            for (int o = 0; o < 16; ++o) {
                const float4* wr = reinterpret_cast<const float4*>(d3_w + o * 8);
                float s0 = sB3[o];
                #pragma unroll
                for (int j = 0; j < 2; ++j) {
                    float4 w = __ldg(wr + j);
                    s0 = fmaf(h2[4*j+0], w.x, s0);
                    s0 = fmaf(h2[4*j+1], w.y, s0);
                    s0 = fmaf(h2[4*j+2], w.z, s0);
                    s0 = fmaf(h2[4*j+3], w.w, s0);
                }
                op[(size_t)o * HW] = s0;
            }
        }
        __syncthreads();   // sOut reads done before next tile overwrites
    }
}

extern "C" void kernel_launch(void* const* d_in, const int* in_sizes, int n_in,
                              void* d_out, int out_size)
{
    cudaFuncSetAttribute(fused_tiled_kernel,
                         cudaFuncAttributeMaxDynamicSharedMemorySize, SMEM_BYTES);
    fused_tiled_kernel<<<NBLK, TPB, SMEM_BYTES>>>(
        (const float*)d_in[0], (const float*)d_in[1],
        (const float*)d_in[2], (const float*)d_in[3],
        (const float*)d_in[4], (const float*)d_in[5],
        (const float*)d_in[6], (const float*)d_in[7],
        (const float*)d_in[8],
        (const float*)d_in[9], (const float*)d_in[10],
        (const float*)d_in[11], (const float*)d_in[12],
        (float*)d_out);
}